// round 3
// baseline (speedup 1.0000x reference)
#include <cuda_runtime.h>
#include <cstdint>
#include <cmath>

// Problem constants
#define T_TOK 1024
#define HDIM  2048
#define NEXP  64
#define IDIM  1024
#define SIDIM 4096
#define KSEL  8
#define NROWS (T_TOK * KSEL)

// GEMM tile config
#define BM 128
#define BN 128          // B rows per tile
#define BK 16
#define SST 20          // smem row stride in floats (conflict-free, 80B = 16B-aligned)
#define NSTAGE 4
#define STAGE_F (128 * SST)                 // floats per A (or B) stage
#define GEMM_SMEM (2 * NSTAGE * STAGE_F * 4 + 512)   // 81920 + 512

// ---------------------------------------------------------------------------
// Device-global scratch
// ---------------------------------------------------------------------------
__device__ float g_h[(size_t)NROWS * IDIM];       // MoE silu*mul      [8192, 1024]
__device__ float g_down[(size_t)NROWS * HDIM];    // MoE down out      [8192, 2048]
__device__ float g_h_s[(size_t)T_TOK * SIDIM];    // shared act        [1024, 4096]
__device__ float g_sh_out[(size_t)T_TOK * HDIM];  // shared MLP out    [1024, 2048]

__device__ int   g_counts[NEXP];
__device__ int   g_offsets[NEXP];
__device__ int   g_fill[NEXP];
__device__ int   g_rowmap[NROWS];
__device__ int   g_row_of_tk[NROWS];
__device__ int   g_top_e[NROWS];
__device__ float g_top_w[NROWS];

// ---------------------------------------------------------------------------
// Helpers
// ---------------------------------------------------------------------------
__device__ __forceinline__ void cp_async16(void* smem, const void* gmem, int src_bytes) {
    uint32_t s = (uint32_t)__cvta_generic_to_shared(smem);
    asm volatile("cp.async.cg.shared.global [%0], [%1], 16, %2;\n"
                 :: "r"(s), "l"(gmem), "r"(src_bytes));
}
__device__ __forceinline__ void cp_commit() { asm volatile("cp.async.commit_group;\n"); }
__device__ __forceinline__ void cp_wait2()  { asm volatile("cp.async.wait_group 2;\n"); }

__device__ __forceinline__ uint32_t f2tf(float f) {
    uint32_t r;
    asm("cvt.rna.tf32.f32 %0, %1;" : "=r"(r) : "f"(f));
    return r;
}

__device__ __forceinline__ void mma_tf32(float c[4],
                                         uint32_t a0, uint32_t a1, uint32_t a2, uint32_t a3,
                                         uint32_t b0, uint32_t b1) {
    asm volatile(
        "mma.sync.aligned.m16n8k8.row.col.f32.tf32.tf32.f32 "
        "{%0,%1,%2,%3},{%4,%5,%6,%7},{%8,%9},{%0,%1,%2,%3};\n"
        : "+f"(c[0]), "+f"(c[1]), "+f"(c[2]), "+f"(c[3])
        : "r"(a0), "r"(a1), "r"(a2), "r"(a3), "r"(b0), "r"(b1));
}

__device__ __forceinline__ float silu_mul(float g, float u) {
    return g * u / (1.f + expf(-g));
}

// ---------------------------------------------------------------------------
// Routing kernels
// ---------------------------------------------------------------------------
__global__ void init_k() {
    int i = threadIdx.x;
    if (i < NEXP) g_counts[i] = 0;
}

__global__ void router_k(const float* __restrict__ x, const float* __restrict__ wg) {
    int t = blockIdx.x;
    __shared__ float xs[HDIM];
    __shared__ float sc[NEXP];
    for (int d = threadIdx.x; d < HDIM; d += blockDim.x) xs[d] = x[(size_t)t * HDIM + d];
    __syncthreads();

    int w = threadIdx.x >> 5, lane = threadIdx.x & 31;
    for (int e = w * 8; e < w * 8 + 8; e++) {
        const float* wr = wg + (size_t)e * HDIM;
        float s = 0.f;
        for (int d = lane; d < HDIM; d += 32) s += xs[d] * wr[d];
        #pragma unroll
        for (int o = 16; o; o >>= 1) s += __shfl_xor_sync(0xffffffffu, s, o);
        if (lane == 0) sc[e] = 1.f / (1.f + expf(-s));
    }
    __syncthreads();

    if (threadIdx.x == 0) {
        for (int k = 0; k < KSEL; k++) {
            int best = 0; float bv = sc[0];
            for (int e = 1; e < NEXP; e++)
                if (sc[e] > bv) { bv = sc[e]; best = e; }
            g_top_e[t * KSEL + k] = best;
            g_top_w[t * KSEL + k] = bv;
            atomicAdd(&g_counts[best], 1);
            sc[best] = -1.f;
        }
    }
}

__global__ void scan_k() {
    if (threadIdx.x == 0) {
        int acc = 0;
        for (int e = 0; e < NEXP; e++) {
            g_offsets[e] = acc;
            g_fill[e] = acc;
            acc += g_counts[e];
        }
    }
}

__global__ void assign_k() {
    int idx = blockIdx.x * blockDim.x + threadIdx.x;
    if (idx >= NROWS) return;
    int e = g_top_e[idx];
    int r = atomicAdd(&g_fill[e], 1);
    g_rowmap[r] = idx >> 3;
    g_row_of_tk[idx] = r;
}

// ---------------------------------------------------------------------------
// TF32 mma.sync GEMM, 4-stage cp.async pipeline.
//   C[m,n] = sum_k A[m,k] * B[n,k]
//   BM=128 (A rows), BN=128 (B rows), BK=16. 256 threads, warps 4(M) x 2(N),
//   warp tile 32x64.
//   ACT: B tile = 64 gate rows + 64 up rows (upOff = start of up region);
//        epilogue writes silu(g)*u -> 64 output cols per CTA.
//   non-ACT: B tile = 128 rows -> 128 output cols per CTA.
// ---------------------------------------------------------------------------
template <bool GATHER, bool EXPERT, bool ACT>
__global__ void __launch_bounds__(256)
gemm2(const float* __restrict__ A, const float* __restrict__ Bw, float* __restrict__ C,
      int Kd, int Nout, long strideBe, int upOff, int Mdense)
{
    extern __shared__ float sm[];
    int e = EXPERT ? blockIdx.z : 0;
    int M, off;
    if (EXPERT) { M = g_counts[e]; off = g_offsets[e]; }
    else        { M = Mdense;      off = 0; }
    int m0 = blockIdx.y * BM;
    if (m0 >= M) return;
    int nb = blockIdx.x;
    const float* B = Bw + (long)e * strideBe;

    int tid = threadIdx.x, warp = tid >> 5, lane = tid & 31;
    int* arows = (int*)(sm + 2 * NSTAGE * STAGE_F);

    if (tid < BM) {
        int gr = m0 + tid;
        int ar = -1;
        if (gr < M) ar = GATHER ? g_rowmap[off + gr] : (off + gr);
        arows[tid] = ar;
    }
    __syncthreads();

    // ---- producer constants: each thread copies 8 floats of A and 8 of B per stage
    int prow = tid >> 1;             // 0..127
    int c8   = (tid & 1) * 8;        // 0 or 8
    int ar   = arows[prow];
    bool aok = (ar >= 0);
    const float* aptr = A + (size_t)(aok ? ar : 0) * Kd + c8;
    int brglob;
    if (ACT) brglob = (prow < 64) ? (nb * 64 + prow) : (upOff + nb * 64 + (prow - 64));
    else     brglob = nb * BN + prow;
    const float* bptr = B + (size_t)brglob * Kd + c8;
    float* dstA0 = sm + prow * SST + c8;                       // stage 0 slot
    float* dstB0 = sm + NSTAGE * STAGE_F + prow * SST + c8;

    auto stage_load = [&](int kt, int s) {
        int k0 = kt * BK;
        float* dA = dstA0 + s * STAGE_F;
        float* dB = dstB0 + s * STAGE_F;
        cp_async16(dA,     aok ? (aptr + k0)     : aptr, aok ? 16 : 0);
        cp_async16(dA + 4, aok ? (aptr + k0 + 4) : aptr, aok ? 16 : 0);
        cp_async16(dB,     bptr + k0,     16);
        cp_async16(dB + 4, bptr + k0 + 4, 16);
    };

    // ---- consumer constants
    int wm = warp & 3;               // 0..3 : M slice (32 rows)
    int wn = warp >> 2;              // 0..1 : N slice (64 B rows)
    int g  = lane >> 2, tg = lane & 3;

    float acc[2][8][4];
    #pragma unroll
    for (int i = 0; i < 2; i++)
        #pragma unroll
        for (int j = 0; j < 8; j++)
            #pragma unroll
            for (int q = 0; q < 4; q++) acc[i][j][q] = 0.f;

    int ktiles = Kd / BK;

    // prologue: stages 0..2
    stage_load(0, 0); cp_commit();
    stage_load(1, 1); cp_commit();
    stage_load(2, 2); cp_commit();

    for (int kt = 0; kt < ktiles; kt++) {
        cp_wait2();
        __syncthreads();
        const float* as = sm + (kt & 3) * STAGE_F;
        const float* bs = sm + (NSTAGE + (kt & 3)) * STAGE_F;

        #pragma unroll
        for (int kk = 0; kk < 16; kk += 8) {
            uint32_t afr[2][4];
            #pragma unroll
            for (int mi = 0; mi < 2; mi++) {
                int rb = wm * 32 + mi * 16;
                afr[mi][0] = f2tf(as[(rb + g    ) * SST + kk + tg    ]);
                afr[mi][1] = f2tf(as[(rb + g + 8) * SST + kk + tg    ]);
                afr[mi][2] = f2tf(as[(rb + g    ) * SST + kk + tg + 4]);
                afr[mi][3] = f2tf(as[(rb + g + 8) * SST + kk + tg + 4]);
            }
            #pragma unroll
            for (int ni = 0; ni < 8; ni++) {
                int brow;
                if (ACT) brow = (ni < 4) ? (wn * 32 + ni * 8) : (64 + wn * 32 + (ni - 4) * 8);
                else     brow = wn * 64 + ni * 8;
                uint32_t b0 = f2tf(bs[(brow + g) * SST + kk + tg    ]);
                uint32_t b1 = f2tf(bs[(brow + g) * SST + kk + tg + 4]);
                mma_tf32(acc[0][ni], afr[0][0], afr[0][1], afr[0][2], afr[0][3], b0, b1);
                mma_tf32(acc[1][ni], afr[1][0], afr[1][1], afr[1][2], afr[1][3], b0, b1);
            }
        }
        if (kt + 3 < ktiles) stage_load(kt + 3, (kt + 3) & 3);
        cp_commit();
    }

    // ---- epilogue
    #pragma unroll
    for (int mi = 0; mi < 2; mi++) {
        int r0 = m0 + wm * 32 + mi * 16 + g;
        bool v0 = r0 < M, v1 = (r0 + 8) < M;
        size_t base0 = (size_t)(off + r0) * Nout;
        size_t base1 = (size_t)(off + r0 + 8) * Nout;
        if (ACT) {
            #pragma unroll
            for (int ni = 0; ni < 4; ni++) {
                int col = nb * 64 + wn * 32 + ni * 8 + tg * 2;
                if (v0) {
                    float2 o;
                    o.x = silu_mul(acc[mi][ni][0], acc[mi][ni + 4][0]);
                    o.y = silu_mul(acc[mi][ni][1], acc[mi][ni + 4][1]);
                    *(float2*)(C + base0 + col) = o;
                }
                if (v1) {
                    float2 o;
                    o.x = silu_mul(acc[mi][ni][2], acc[mi][ni + 4][2]);
                    o.y = silu_mul(acc[mi][ni][3], acc[mi][ni + 4][3]);
                    *(float2*)(C + base1 + col) = o;
                }
            }
        } else {
            #pragma unroll
            for (int ni = 0; ni < 8; ni++) {
                int col = nb * BN + wn * 64 + ni * 8 + tg * 2;
                if (v0) {
                    float2 o; o.x = acc[mi][ni][0]; o.y = acc[mi][ni][1];
                    *(float2*)(C + base0 + col) = o;
                }
                if (v1) {
                    float2 o; o.x = acc[mi][ni][2]; o.y = acc[mi][ni][3];
                    *(float2*)(C + base1 + col) = o;
                }
            }
        }
    }
}

// ---------------------------------------------------------------------------
// Combine
// ---------------------------------------------------------------------------
__global__ void combine_k(float* __restrict__ out) {
    int t = blockIdx.x;
    __shared__ int   rws[KSEL];
    __shared__ float ws[KSEL];
    if (threadIdx.x < KSEL) {
        rws[threadIdx.x] = g_row_of_tk[t * KSEL + threadIdx.x];
        ws[threadIdx.x]  = g_top_w[t * KSEL + threadIdx.x];
    }
    __syncthreads();
    for (int d = threadIdx.x; d < HDIM; d += blockDim.x) {
        float a = g_sh_out[(size_t)t * HDIM + d];
        float m = 0.f;
        #pragma unroll
        for (int k = 0; k < KSEL; k++)
            m += ws[k] * g_down[(size_t)rws[k] * HDIM + d];
        out[(size_t)t * HDIM + d] = (a + 8.f * m) * (1.f / 9.f);
    }
}

// ---------------------------------------------------------------------------
// kernel_launch — graph-capturable, allocation-free
// ---------------------------------------------------------------------------
extern "C" void kernel_launch(void* const* d_in, const int* in_sizes, int n_in,
                              void* d_out, int out_size)
{
    const float* x      = (const float*)d_in[0];
    const float* w_gate = (const float*)d_in[1];
    const float* w13    = (const float*)d_in[2];
    const float* w2     = (const float*)d_in[3];
    const float* wsg    = (const float*)d_in[4];
    const float* wsd    = (const float*)d_in[5];
    float* out = (float*)d_out;

    float *p_h, *p_down, *p_h_s, *p_sh_out;
    cudaGetSymbolAddress((void**)&p_h,      g_h);
    cudaGetSymbolAddress((void**)&p_down,   g_down);
    cudaGetSymbolAddress((void**)&p_h_s,    g_h_s);
    cudaGetSymbolAddress((void**)&p_sh_out, g_sh_out);

    cudaFuncSetAttribute(gemm2<true,  true,  true >, cudaFuncAttributeMaxDynamicSharedMemorySize, GEMM_SMEM);
    cudaFuncSetAttribute(gemm2<false, true,  false>, cudaFuncAttributeMaxDynamicSharedMemorySize, GEMM_SMEM);
    cudaFuncSetAttribute(gemm2<false, false, true >, cudaFuncAttributeMaxDynamicSharedMemorySize, GEMM_SMEM);
    cudaFuncSetAttribute(gemm2<false, false, false>, cudaFuncAttributeMaxDynamicSharedMemorySize, GEMM_SMEM);

    // routing
    init_k<<<1, 64>>>();
    router_k<<<T_TOK, 256>>>(x, w_gate);
    scan_k<<<1, 32>>>();
    assign_k<<<NROWS / 256, 256>>>();

    // MoE gate_up (+ fused silu*mul): h[8192,1024] = act(gather(x) @ w13[e]^T)
    gemm2<true, true, true><<<dim3(IDIM / 64, 8, NEXP), 256, GEMM_SMEM>>>(
        x, w13, p_h, HDIM, IDIM, (long)2 * IDIM * HDIM, IDIM, 0);

    // MoE down: down[8192,2048] = h @ w2[e]^T
    gemm2<false, true, false><<<dim3(HDIM / BN, 8, NEXP), 256, GEMM_SMEM>>>(
        p_h, w2, p_down, IDIM, HDIM, (long)HDIM * IDIM, 0, 0);

    // Shared gate_up (+ act): h_s[1024,4096] = act(x @ wsg^T)
    gemm2<false, false, true><<<dim3(SIDIM / 64, T_TOK / BM, 1), 256, GEMM_SMEM>>>(
        x, wsg, p_h_s, HDIM, SIDIM, 0, SIDIM, T_TOK);

    // Shared down: sh_out[1024,2048] = h_s @ wsd^T
    gemm2<false, false, false><<<dim3(HDIM / BN, T_TOK / BM, 1), 256, GEMM_SMEM>>>(
        p_h_s, wsd, p_sh_out, SIDIM, HDIM, 0, 0, T_TOK);

    // Combine
    combine_k<<<T_TOK, 256>>>(out);
}